// round 15
// baseline (speedup 1.0000x reference)
#include <cuda_runtime.h>
#include <cuda_bf16.h>

// ---------------------------------------------------------------------------
// EventGRUBayes — two-kernel split.
// K1: warp-independent recurrence (128 blk x 128 thr, 4 warps x 2 samples).
//     ODE gate matrices (ghr/ghz/ghh) AND event matrix gWhh stored as packed
//     bf16x2 in smem; unpacked with shift/mask (alu pipe, exact widening)
//     into packed fma.rn.f32x2. Wih + biases stay fp32. ODE u-gate uses
//     tanh.approx.f32 (error damped by DT). h_rec streamed to g_hrec.
// K2: batched head v3 (8 pairs/warp, looped batches + cp.async). [UNCHANGED]
// ---------------------------------------------------------------------------

#define B_     1024
#define NEV    400
#define NSTEPS 500
#define TOT_   (NEV * 256)
#define DT_    0.01f

typedef unsigned long long ull;
typedef ulonglong2 ul2;

// K1 smem offsets in 4-byte units. bf16 rows: 32 u32 + 4 pad = stride 36.
#define UW_GHR 0
#define UW_GHZ 2304
#define UW_GHH 4608
#define UW_WHH 6912          // 192 rows x 36 -> ends 13824
#define OF_WIH 13824         // fp32, 192 rows x 12
#define OF_BIH 16128
#define OF_BHH 16320
#define OF_GXB 16512
#define OF_HS  16704
#define OF_RS  17216
#define OF_WIN 17728         // [2][8] ints
#define OF_XV  17744         // [2][8][8]
#define SM_MAIN 17872        // 71488 bytes

// K2 smem float offsets
#define SH_W1  0             // 128*68
#define SH_HB  8704          // 8 warps * 2 buffers * 512
#define SH_OB1 16896
#define SH_W2  17024
#define SH_OB2 17280
#define SM_HEAD 17282        // 69128 bytes

#define HEAD_L      6
#define HEAD_BLOCKS 1336     // 1336*8*48 = 513024 pairs

__device__ int   g_winner[NEV * B_];
__device__ float g_hrec[(size_t)(NSTEPS + 1) * B_ * 64];   // [t][b][64]

__global__ void winner_init_k() {
    int i = blockIdx.x * blockDim.x + threadIdx.x;
    if (i < NEV * B_) g_winner[i] = -1;
}
__global__ void winner_scatter_k(const int* __restrict__ sid) {
    int j = blockIdx.x * blockDim.x + threadIdx.x;
    if (j < TOT_) atomicMax(&g_winner[(j >> 8) * B_ + sid[j]], j);
}

__device__ __forceinline__ float sigm(float x) {
    return __fdividef(1.f, 1.f + __expf(-x));
}
__device__ __forceinline__ float tanh_f(float x) {        // exact-ish (events, h0)
    float xc = fminf(fmaxf(x, -15.f), 15.f);
    float e  = __expf(-2.f * xc);
    return __fdividef(1.f - e, 1.f + e);
}
__device__ __forceinline__ float tanh_fast(float x) {     // MUFU.TANH (ODE only)
    float y; asm("tanh.approx.f32 %0, %1;" : "=f"(y) : "f"(x));
    return y;
}
#define FMA2(d, a, b, c) \
    asm("fma.rn.f32x2 %0, %1, %2, %3;" : "=l"(d) : "l"(a), "l"(b), "l"(c))
__device__ __forceinline__ float hadd2(ull v) {
    unsigned lo, hi;
    asm("mov.b64 {%0, %1}, %2;" : "=r"(lo), "=r"(hi) : "l"(v));
    return __uint_as_float(lo) + __uint_as_float(hi);
}
// packed bf16x2 -> packed f32x2 (exact widening: shift / mask + pack)
__device__ __forceinline__ ull bf2up(unsigned u) {
    unsigned lo = u << 16;
    unsigned hi = u & 0xffff0000u;
    ull r; asm("mov.b64 %0, {%1, %2};" : "=l"(r) : "r"(lo), "r"(hi));
    return r;
}
__device__ __forceinline__ unsigned packbf(float a, float b) {
    __nv_bfloat162 t = __floats2bfloat162_rn(a, b);   // a->low, b->high
    unsigned u; __builtin_memcpy(&u, &t, 4);
    return u;
}
__device__ __forceinline__ float dot8(const float* __restrict__ w, float4 xa, float4 xb) {
    float4 A  = *reinterpret_cast<const float4*>(w);
    float4 Bv = *reinterpret_cast<const float4*>(w + 4);
    float s = A.x * xa.x;
    s = fmaf(A.y,  xa.y, s); s = fmaf(A.z,  xa.z, s); s = fmaf(A.w,  xa.w, s);
    s = fmaf(Bv.x, xb.x, s); s = fmaf(Bv.y, xb.y, s);
    s = fmaf(Bv.z, xb.z, s); s = fmaf(Bv.w, xb.w, s);
    return s;
}
#define CP_ASYNC16(saddr, gptr) \
    asm volatile("cp.async.cg.shared.global [%0], [%1], 16;" \
                 :: "r"(saddr), "l"(gptr) : "memory")
#define CP_COMMIT()  asm volatile("cp.async.commit_group;" ::: "memory")
#define CP_WAIT0()   asm volatile("cp.async.wait_group 0;" ::: "memory")

// GRU-Bayes event update, one sample, warp-collective. Whh bf16, Wih fp32.
__device__ __forceinline__ void event_upd(
    float* __restrict__ hs, const float* __restrict__ xv,
    const float* __restrict__ sm, const unsigned* __restrict__ usm,
    float ebr1, float ebr2, float ebz1, float ebz2,
    float ebi1, float ebi2, float ebh1, float ebh2,
    int lane, int o2)
{
    float4 xa = *(const float4*)xv, xb = *(const float4*)(xv + 4);
    float gir1 = dot8(sm + OF_WIH + lane*12,       xa, xb);
    float gir2 = dot8(sm + OF_WIH + (32+lane)*12,  xa, xb);
    float giz1 = dot8(sm + OF_WIH + (64+lane)*12,  xa, xb);
    float giz2 = dot8(sm + OF_WIH + (96+lane)*12,  xa, xb);
    float gin1 = dot8(sm + OF_WIH + (128+lane)*12, xa, xb);
    float gin2 = dot8(sm + OF_WIH + (160+lane)*12, xa, xb);
    const uint4* qE = (const uint4*)(usm + UW_WHH + lane*36);
    // rowset stride: 32 rows * 36 u32 = 1152 u32 = 288 uint4
    ull a1=0,a2=0,a3=0,a4=0,a5=0,a6=0;
    const ul2* hp = (const ul2*)hs;
    #pragma unroll
    for (int i = 0; i < 8; i++) {
        ul2 h0 = hp[2*i], h1 = hp[2*i+1];
        uint4 q; ull w0, w1, w2, w3;
        q = qE[i];
        w0=bf2up(q.x); w1=bf2up(q.y); w2=bf2up(q.z); w3=bf2up(q.w);
        FMA2(a1,w0,h0.x,a1); FMA2(a1,w1,h0.y,a1);
        FMA2(a1,w2,h1.x,a1); FMA2(a1,w3,h1.y,a1);
        q = qE[i + 288];
        w0=bf2up(q.x); w1=bf2up(q.y); w2=bf2up(q.z); w3=bf2up(q.w);
        FMA2(a2,w0,h0.x,a2); FMA2(a2,w1,h0.y,a2);
        FMA2(a2,w2,h1.x,a2); FMA2(a2,w3,h1.y,a2);
        q = qE[i + 576];
        w0=bf2up(q.x); w1=bf2up(q.y); w2=bf2up(q.z); w3=bf2up(q.w);
        FMA2(a3,w0,h0.x,a3); FMA2(a3,w1,h0.y,a3);
        FMA2(a3,w2,h1.x,a3); FMA2(a3,w3,h1.y,a3);
        q = qE[i + 864];
        w0=bf2up(q.x); w1=bf2up(q.y); w2=bf2up(q.z); w3=bf2up(q.w);
        FMA2(a4,w0,h0.x,a4); FMA2(a4,w1,h0.y,a4);
        FMA2(a4,w2,h1.x,a4); FMA2(a4,w3,h1.y,a4);
        q = qE[i + 1152];
        w0=bf2up(q.x); w1=bf2up(q.y); w2=bf2up(q.z); w3=bf2up(q.w);
        FMA2(a5,w0,h0.x,a5); FMA2(a5,w1,h0.y,a5);
        FMA2(a5,w2,h1.x,a5); FMA2(a5,w3,h1.y,a5);
        q = qE[i + 1440];
        w0=bf2up(q.x); w1=bf2up(q.y); w2=bf2up(q.z); w3=bf2up(q.w);
        FMA2(a6,w0,h0.x,a6); FMA2(a6,w1,h0.y,a6);
        FMA2(a6,w2,h1.x,a6); FMA2(a6,w3,h1.y,a6);
    }
    float h1o = hs[lane], h2o = hs[o2];
    float r1 = sigm(gir1 + hadd2(a1) + ebr1);
    float r2 = sigm(gir2 + hadd2(a2) + ebr2);
    float z1 = sigm(giz1 + hadd2(a3) + ebz1);
    float z2 = sigm(giz2 + hadd2(a4) + ebz2);
    float n1 = tanh_f(gin1 + ebi1 + r1 * (hadd2(a5) + ebh1));
    float n2 = tanh_f(gin2 + ebi2 + r2 * (hadd2(a6) + ebh2));
    float h1n = fmaf(z1, h1o - n1, n1);      // (1-z)n + z h
    float h2n = fmaf(z2, h2o - n2, n2);
    __syncwarp();
    hs[lane] = h1n; hs[o2] = h2n;
    __syncwarp();
}

__global__ __launch_bounds__(128, 1)
void ev_gru_main(
    const float* __restrict__ X,
    const float* __restrict__ covs,
    const float* __restrict__ cW1, const float* __restrict__ cb1,
    const float* __restrict__ cW2, const float* __restrict__ cb2,
    const float* __restrict__ gWih, const float* __restrict__ gWhh,
    const float* __restrict__ gbih, const float* __restrict__ gbhh,
    const float* __restrict__ gxb,
    const float* __restrict__ ghrW, const float* __restrict__ ghzW,
    const float* __restrict__ ghhW)
{
    extern __shared__ float sm[];
    unsigned* usm = (unsigned*)sm;
    const int tid = threadIdx.x, blk = blockIdx.x;
    const int warp = tid >> 5, lane = tid & 31, o2 = lane + 32;
    int* swin = (int*)(sm + OF_WIN);

    // ---- staging: bf16x2-packed gate + Whh matrices, fp32 Wih/biases ----
    for (int i = tid; i < 64*32; i += 128) {
        int r = i >> 5, p = i & 31, c = p * 2;
        usm[UW_GHR + r*36 + p] = packbf(ghrW[r*64 + c], ghrW[r*64 + c + 1]);
        usm[UW_GHZ + r*36 + p] = packbf(ghzW[r*64 + c], ghzW[r*64 + c + 1]);
        usm[UW_GHH + r*36 + p] = packbf(ghhW[r*64 + c], ghhW[r*64 + c + 1]);
    }
    for (int i = tid; i < 192*32; i += 128) {
        int r = i >> 5, p = i & 31, c = p * 2;
        usm[UW_WHH + r*36 + p] = packbf(gWhh[r*64 + c], gWhh[r*64 + c + 1]);
    }
    for (int i = tid; i < 192*8; i += 128) {
        int r = i >> 3, c = i & 7;
        sm[OF_WIH + r*12 + c] = gWih[i];
    }
    for (int i = tid; i < 192; i += 128) {
        sm[OF_BIH + i] = gbih[i];
        sm[OF_BHH + i] = gbhh[i];
        sm[OF_GXB + i] = gxb[i];
    }

    const int sA = warp*2, sB = sA + 1;
    const int bA = blk*8 + sA, bB = bA + 1;
    float* hA = sm + OF_HS + sA*64;  float* hB = sm + OF_HS + sB*64;
    float* rA = sm + OF_RS + sA*64;  float* rB = sm + OF_RS + sB*64;

    // ---- h0 init (warp-local, 2 samples, fp32 global weights) ----
    #pragma unroll
    for (int pick = 0; pick < 2; pick++) {
        const int b = pick ? bB : bA;
        float* hs = pick ? hB : hA;
        float* rs = pick ? rB : rA;
        float t1 = __ldg(cb1 + lane), t2 = __ldg(cb1 + o2);
        #pragma unroll
        for (int k = 0; k < 16; k++) {
            float cv = __ldg(covs + b*16 + k);
            t1 = fmaf(cv, __ldg(cW1 + lane*16 + k), t1);
            t2 = fmaf(cv, __ldg(cW1 + o2*16   + k), t2);
        }
        rs[lane] = fmaxf(t1, 0.f); rs[o2] = fmaxf(t2, 0.f);
        __syncwarp();
        float a1 = __ldg(cb2 + lane), a2 = __ldg(cb2 + o2);
        #pragma unroll 8
        for (int c = 0; c < 64; c++) {
            float tv = rs[c];
            a1 = fmaf(tv, __ldg(cW2 + lane*64 + c), a1);
            a2 = fmaf(tv, __ldg(cW2 + o2*64   + c), a2);
        }
        __syncwarp();
        hs[lane] = tanh_f(a1); hs[o2] = tanh_f(a2);
        __syncwarp();
    }
    // t=0 winner/X prefetch (warp-local)
    if (lane < 2) {
        int w = __ldg(g_winner + bA + lane);
        swin[sA + lane] = w;
        if (w >= 0) {
            const float4* xp = (const float4*)(X + (size_t)w*8);
            float4 xa = __ldg(xp), xb = __ldg(xp + 1);
            float4* dst = (float4*)(sm + OF_XV + (sA + lane)*8);
            dst[0] = xa; dst[1] = xb;
        }
    }
    __syncthreads();   // staging done (one-time)

    // ---- stationary pointers / scalars ----
    const uint4* qR1 = (const uint4*)(usm + UW_GHR + lane*36);
    const uint4* qR2 = (const uint4*)(usm + UW_GHR + (lane+32)*36);
    const uint4* qZ1 = (const uint4*)(usm + UW_GHZ + lane*36);
    const uint4* qZ2 = (const uint4*)(usm + UW_GHZ + (lane+32)*36);
    const uint4* qU1 = (const uint4*)(usm + UW_GHH + lane*36);
    const uint4* qU2 = (const uint4*)(usm + UW_GHH + (lane+32)*36);
    const ul2* hpA = (const ul2*)hA;  const ul2* hpB = (const ul2*)hB;
    const ul2* rpA = (const ul2*)rA;  const ul2* rpB = (const ul2*)rB;

    const float xr1 = sm[OF_GXB + lane],       xr2 = sm[OF_GXB + o2];
    const float xz1 = sm[OF_GXB + 64 + lane],  xz2 = sm[OF_GXB + 64 + o2];
    const float xh1 = sm[OF_GXB + 128 + lane], xh2 = sm[OF_GXB + 128 + o2];
    const float ebr1 = sm[OF_BIH + lane]      + sm[OF_BHH + lane];
    const float ebr2 = sm[OF_BIH + o2]        + sm[OF_BHH + o2];
    const float ebz1 = sm[OF_BIH + 64 + lane] + sm[OF_BHH + 64 + lane];
    const float ebz2 = sm[OF_BIH + 64 + o2]   + sm[OF_BHH + 64 + o2];
    const float ebi1 = sm[OF_BIH + 128 + lane], ebi2 = sm[OF_BIH + 128 + o2];
    const float ebh1 = sm[OF_BHH + 128 + lane], ebh2 = sm[OF_BHH + 128 + o2];

    // ================= main loop (warp-independent) =================
    for (int t = 0; ; t++) {
        const int pb = t & 1;

        // ---- events (last-dup wins; from pre-update h) ----
        if (t < NEV) {
            if (swin[pb*8 + sA] >= 0)
                event_upd(hA, sm + OF_XV + pb*64 + sA*8, sm, usm,
                          ebr1,ebr2,ebz1,ebz2,ebi1,ebi2,ebh1,ebh2, lane, o2);
            if (swin[pb*8 + sB] >= 0)
                event_upd(hB, sm + OF_XV + pb*64 + sB*8, sm, usm,
                          ebr1,ebr2,ebz1,ebz2,ebi1,ebi2,ebh1,ebh2, lane, o2);
        }

        // ---- h_rec store (post-event, pre-ODE) ----
        {
            float* base = g_hrec + ((size_t)t*B_ + bA)*64;
            float2 vA = *(const float2*)(hA + lane*2);
            float2 vB = *(const float2*)(hB + lane*2);
            *(float2*)(base + lane*2)      = vA;
            *(float2*)(base + 64 + lane*2) = vB;
        }
        if (t == NSTEPS) break;

        // warp-local prefetch of winners for t+1
        int pw = -1;
        const bool pf = (t + 1 < NEV) && (lane < 2);
        if (pf) pw = __ldg(g_winner + (t+1)*B_ + bA + lane);

        // ---- PASS1: gates r,z — bf16 weights unpacked to FMA2 ----
        ull aR1A=0, aR1B=0, aR2A=0, aR2B=0, aZ1A=0, aZ1B=0, aZ2A=0, aZ2B=0;
        #pragma unroll
        for (int i = 0; i < 8; i++) {
            ul2 a0 = hpA[2*i], a1 = hpA[2*i+1];
            ul2 b0 = hpB[2*i], b1 = hpB[2*i+1];
            uint4 q; ull w0, w1, w2, w3;
            q = qR1[i];
            w0 = bf2up(q.x); w1 = bf2up(q.y); w2 = bf2up(q.z); w3 = bf2up(q.w);
            FMA2(aR1A,w0,a0.x,aR1A); FMA2(aR1A,w1,a0.y,aR1A);
            FMA2(aR1A,w2,a1.x,aR1A); FMA2(aR1A,w3,a1.y,aR1A);
            FMA2(aR1B,w0,b0.x,aR1B); FMA2(aR1B,w1,b0.y,aR1B);
            FMA2(aR1B,w2,b1.x,aR1B); FMA2(aR1B,w3,b1.y,aR1B);
            q = qR2[i];
            w0 = bf2up(q.x); w1 = bf2up(q.y); w2 = bf2up(q.z); w3 = bf2up(q.w);
            FMA2(aR2A,w0,a0.x,aR2A); FMA2(aR2A,w1,a0.y,aR2A);
            FMA2(aR2A,w2,a1.x,aR2A); FMA2(aR2A,w3,a1.y,aR2A);
            FMA2(aR2B,w0,b0.x,aR2B); FMA2(aR2B,w1,b0.y,aR2B);
            FMA2(aR2B,w2,b1.x,aR2B); FMA2(aR2B,w3,b1.y,aR2B);
            q = qZ1[i];
            w0 = bf2up(q.x); w1 = bf2up(q.y); w2 = bf2up(q.z); w3 = bf2up(q.w);
            FMA2(aZ1A,w0,a0.x,aZ1A); FMA2(aZ1A,w1,a0.y,aZ1A);
            FMA2(aZ1A,w2,a1.x,aZ1A); FMA2(aZ1A,w3,a1.y,aZ1A);
            FMA2(aZ1B,w0,b0.x,aZ1B); FMA2(aZ1B,w1,b0.y,aZ1B);
            FMA2(aZ1B,w2,b1.x,aZ1B); FMA2(aZ1B,w3,b1.y,aZ1B);
            q = qZ2[i];
            w0 = bf2up(q.x); w1 = bf2up(q.y); w2 = bf2up(q.z); w3 = bf2up(q.w);
            FMA2(aZ2A,w0,a0.x,aZ2A); FMA2(aZ2A,w1,a0.y,aZ2A);
            FMA2(aZ2A,w2,a1.x,aZ2A); FMA2(aZ2A,w3,a1.y,aZ2A);
            FMA2(aZ2B,w0,b0.x,aZ2B); FMA2(aZ2B,w1,b0.y,aZ2B);
            FMA2(aZ2B,w2,b1.x,aZ2B); FMA2(aZ2B,w3,b1.y,aZ2B);
        }
        float h1A = hA[lane], h2A = hA[o2];
        float h1B = hB[lane], h2B = hB[o2];
        float r1A = sigm(hadd2(aR1A) + xr1), r2A = sigm(hadd2(aR2A) + xr2);
        float r1B = sigm(hadd2(aR1B) + xr1), r2B = sigm(hadd2(aR2B) + xr2);
        float z1A = sigm(hadd2(aZ1A) + xz1), z2A = sigm(hadd2(aZ2A) + xz2);
        float z1B = sigm(hadd2(aZ1B) + xz1), z2B = sigm(hadd2(aZ2B) + xz2);
        __syncwarp();
        rA[lane] = r1A * h1A; rA[o2] = r2A * h2A;
        rB[lane] = r1B * h1B; rB[o2] = r2B * h2B;
        if (pf) {
            swin[(pb ^ 1)*8 + sA + lane] = pw;
            if (pw >= 0) {
                const float4* xp = (const float4*)(X + (size_t)pw*8);
                float4 xa = __ldg(xp), xb = __ldg(xp + 1);
                float4* dst = (float4*)(sm + OF_XV + (pb^1)*64 + (sA+lane)*8);
                dst[0] = xa; dst[1] = xb;
            }
        }
        __syncwarp();

        // ---- PASS2: ghh (bf16) on (r*h); Euler update (fast tanh) ----
        ull u1A=0, u1B=0, u2A=0, u2B=0;
        #pragma unroll
        for (int i = 0; i < 8; i++) {
            ul2 a0 = rpA[2*i], a1 = rpA[2*i+1];
            ul2 b0 = rpB[2*i], b1 = rpB[2*i+1];
            uint4 q; ull w0, w1, w2, w3;
            q = qU1[i];
            w0 = bf2up(q.x); w1 = bf2up(q.y); w2 = bf2up(q.z); w3 = bf2up(q.w);
            FMA2(u1A,w0,a0.x,u1A); FMA2(u1A,w1,a0.y,u1A);
            FMA2(u1A,w2,a1.x,u1A); FMA2(u1A,w3,a1.y,u1A);
            FMA2(u1B,w0,b0.x,u1B); FMA2(u1B,w1,b0.y,u1B);
            FMA2(u1B,w2,b1.x,u1B); FMA2(u1B,w3,b1.y,u1B);
            q = qU2[i];
            w0 = bf2up(q.x); w1 = bf2up(q.y); w2 = bf2up(q.z); w3 = bf2up(q.w);
            FMA2(u2A,w0,a0.x,u2A); FMA2(u2A,w1,a0.y,u2A);
            FMA2(u2A,w2,a1.x,u2A); FMA2(u2A,w3,a1.y,u2A);
            FMA2(u2B,w0,b0.x,u2B); FMA2(u2B,w1,b0.y,u2B);
            FMA2(u2B,w2,b1.x,u2B); FMA2(u2B,w3,b1.y,u2B);
        }
        float uu1A = tanh_fast(xh1 + hadd2(u1A)), uu2A = tanh_fast(xh2 + hadd2(u2A));
        float uu1B = tanh_fast(xh1 + hadd2(u1B)), uu2B = tanh_fast(xh2 + hadd2(u2B));
        float h1An = fmaf(DT_*(1.f - z1A), uu1A - h1A, h1A);
        float h2An = fmaf(DT_*(1.f - z2A), uu2A - h2A, h2A);
        float h1Bn = fmaf(DT_*(1.f - z1B), uu1B - h1B, h1B);
        float h2Bn = fmaf(DT_*(1.f - z2B), uu2B - h2B, h2B);
        __syncwarp();
        hA[lane] = h1An; hA[o2] = h2An;
        hB[lane] = h1Bn; hB[o2] = h2Bn;
        __syncwarp();
    }
}

// ---------------- K2: batched head v3 (looped batches + cp.async) ----------
__global__ __launch_bounds__(256, 2)
void head_k(const float* __restrict__ oW1, const float* __restrict__ ob1,
            const float* __restrict__ oW2, const float* __restrict__ ob2,
            float* __restrict__ out)
{
    extern __shared__ float sm[];
    const int tid = threadIdx.x, warp = tid >> 5, lane = tid & 31;

    for (int i = tid; i < 128*64; i += 256) {
        int r = i >> 6, c = i & 63;
        sm[SH_W1 + r*68 + c] = oW1[i];
    }
    if (tid < 128) sm[SH_OB1 + tid] = ob1[tid];
    sm[SH_W2 + tid] = oW2[tid];
    if (tid < 2) sm[SH_OB2 + tid] = ob2[tid];

    const size_t warpbase = ((size_t)blockIdx.x*8 + warp) * (8*HEAD_L);
    const unsigned sbuf0 = (unsigned)__cvta_generic_to_shared(sm + SH_HB + warp*1024);
    const unsigned sbuf1 = sbuf0 + 512*4;

    {
        const float* g = g_hrec + warpbase*64;
        #pragma unroll
        for (int k = 0; k < 4; k++)
            CP_ASYNC16(sbuf0 + (lane + k*32)*16, g + (lane + k*32)*4);
        CP_COMMIT();
    }
    __syncthreads();
    CP_WAIT0();
    __syncwarp();

    const ul2* pA = (const ul2*)(sm + SH_W1 + lane*68);
    const ul2* pB = (const ul2*)(sm + SH_W1 + (lane+32)*68);
    const ul2* pC = (const ul2*)(sm + SH_W1 + (lane+64)*68);
    const ul2* pD = (const ul2*)(sm + SH_W1 + (lane+96)*68);
    const float bo0 = sm[SH_OB1 + lane],      bo1 = sm[SH_OB1 + lane + 32];
    const float bo2 = sm[SH_OB1 + lane + 64], bo3 = sm[SH_OB1 + lane + 96];
    const float wa0 = sm[SH_W2 + lane],        wa1 = sm[SH_W2 + 128 + lane];
    const float wb0 = sm[SH_W2 + 32 + lane],   wb1 = sm[SH_W2 + 160 + lane];
    const float wc0 = sm[SH_W2 + 64 + lane],   wc1 = sm[SH_W2 + 192 + lane];
    const float wd0 = sm[SH_W2 + 96 + lane],   wd1 = sm[SH_W2 + 224 + lane];
    const float b20 = sm[SH_OB2], b21 = sm[SH_OB2 + 1];

    for (int l = 0; l < HEAD_L; l++) {
        const int pb = l & 1;
        if (l + 1 < HEAD_L) {
            const float* g = g_hrec + (warpbase + (size_t)(l+1)*8)*64;
            const unsigned dst = pb ? sbuf0 : sbuf1;
            #pragma unroll
            for (int k = 0; k < 4; k++)
                CP_ASYNC16(dst + (lane + k*32)*16, g + (lane + k*32)*4);
            CP_COMMIT();
        }
        const ul2* hw = (const ul2*)(sm + SH_HB + warp*1024 + pb*512);

        ull aA[8], aB[8], aC[8], aD[8];
        #pragma unroll
        for (int p = 0; p < 8; p++) { aA[p]=0; aB[p]=0; aC[p]=0; aD[p]=0; }
        #pragma unroll
        for (int i = 0; i < 16; i++) {
            ul2 wa = pA[i], wb = pB[i], wc = pC[i], wd = pD[i];
            #pragma unroll
            for (int p = 0; p < 8; p++) {
                ul2 hv = hw[p*16 + i];
                FMA2(aA[p], wa.x, hv.x, aA[p]); FMA2(aA[p], wa.y, hv.y, aA[p]);
                FMA2(aB[p], wb.x, hv.x, aB[p]); FMA2(aB[p], wb.y, hv.y, aB[p]);
                FMA2(aC[p], wc.x, hv.x, aC[p]); FMA2(aC[p], wc.y, hv.y, aC[p]);
                FMA2(aD[p], wd.x, hv.x, aD[p]); FMA2(aD[p], wd.y, hv.y, aD[p]);
            }
        }
        const size_t base = warpbase + (size_t)l*8;
        #pragma unroll
        for (int p = 0; p < 8; p++) {
            float d0 = fmaxf(hadd2(aA[p]) + bo0, 0.f);
            float d1 = fmaxf(hadd2(aB[p]) + bo1, 0.f);
            float d2 = fmaxf(hadd2(aC[p]) + bo2, 0.f);
            float d3 = fmaxf(hadd2(aD[p]) + bo3, 0.f);
            float p0 = d0*wa0; p0 = fmaf(d1,wb0,p0); p0 = fmaf(d2,wc0,p0); p0 = fmaf(d3,wd0,p0);
            float p1 = d0*wa1; p1 = fmaf(d1,wb1,p1); p1 = fmaf(d2,wc1,p1); p1 = fmaf(d3,wd1,p1);
            #pragma unroll
            for (int s = 16; s > 0; s >>= 1) {
                p0 += __shfl_xor_sync(0xffffffffu, p0, s);
                p1 += __shfl_xor_sync(0xffffffffu, p1, s);
            }
            if (lane == 0) {
                float2 v = {p0 + b20, p1 + b21};
                *(float2*)(out + (base + p)*2) = v;
            }
        }
        if (l + 1 < HEAD_L) {
            CP_WAIT0();
            __syncwarp();
        }
    }
}

extern "C" void kernel_launch(void* const* d_in, const int* in_sizes, int n_in,
                              void* d_out, int out_size)
{
    (void)in_sizes; (void)n_in; (void)out_size;
    const float* X    = (const float*)d_in[2];
    const int*   sid  = (const int*)  d_in[3];
    const float* covs = (const float*)d_in[4];
    const float* cW1  = (const float*)d_in[6];
    const float* cb1  = (const float*)d_in[7];
    const float* cW2  = (const float*)d_in[8];
    const float* cb2  = (const float*)d_in[9];
    const float* gWih = (const float*)d_in[10];
    const float* gWhh = (const float*)d_in[11];
    const float* gbih = (const float*)d_in[12];
    const float* gbhh = (const float*)d_in[13];
    const float* gxb  = (const float*)d_in[15];
    const float* ghrW = (const float*)d_in[16];
    const float* ghzW = (const float*)d_in[17];
    const float* ghhW = (const float*)d_in[18];
    const float* oW1  = (const float*)d_in[19];
    const float* ob1  = (const float*)d_in[20];
    const float* oW2  = (const float*)d_in[21];
    const float* ob2  = (const float*)d_in[22];
    float* out = (float*)d_out;

    winner_init_k<<<(NEV*B_ + 255)/256, 256>>>();
    winner_scatter_k<<<(TOT_ + 255)/256, 256>>>(sid);

    size_t sm_main = SM_MAIN * sizeof(float);
    cudaFuncSetAttribute(ev_gru_main, cudaFuncAttributeMaxDynamicSharedMemorySize, (int)sm_main);
    ev_gru_main<<<B_/8, 128, sm_main>>>(X, covs, cW1, cb1, cW2, cb2,
                                        gWih, gWhh, gbih, gbhh, gxb,
                                        ghrW, ghzW, ghhW);

    size_t sm_head = SM_HEAD * sizeof(float);
    cudaFuncSetAttribute(head_k, cudaFuncAttributeMaxDynamicSharedMemorySize, (int)sm_head);
    head_k<<<HEAD_BLOCKS, 256, sm_head>>>(oW1, ob1, oW2, ob2, out);
}

// round 16
// speedup vs baseline: 1.1213x; 1.1213x over previous
#include <cuda_runtime.h>
#include <cuda_bf16.h>

// ---------------------------------------------------------------------------
// EventGRUBayes — two-kernel split (R13 + ODE tanh.approx only).
// K1: warp-independent recurrence (128 blk x 128 thr, 4 warps x 2 samples).
//     ODE gate matrices (ghr/ghz/ghh) stored as packed bf16x2 in smem
//     (halves crossbar bytes); unpacked with SHF/LOP3 (alu pipe, exact) and
//     fed to packed fma.rn.f32x2. Event matrices stay fp32 (undamped error
//     path — R14 showed bf16 there costs both time and accuracy). ODE u-gate
//     uses tanh.approx.f32 (error damped by DT*(1-z)). h_rec -> g_hrec.
// K2: batched head v3 (8 pairs/warp, looped batches + cp.async). [UNCHANGED]
// ---------------------------------------------------------------------------

#define B_     1024
#define NEV    400
#define NSTEPS 500
#define TOT_   (NEV * 256)
#define DT_    0.01f

typedef unsigned long long ull;
typedef ulonglong2 ul2;

// K1 smem offsets in 4-byte units. bf16 rows: 32 u32 + 4 pad = stride 36
// (144B = 9x16B, odd 16B-stride -> conflict-free LDS.128).
#define UW_GHR 0
#define UW_GHZ 2304
#define UW_GHH 4608          // ends 6912
#define OF_WHH 6912          // fp32, 192 rows x 68
#define OF_WIH 19968         // fp32, 192 rows x 12
#define OF_BIH 22272
#define OF_BHH 22464
#define OF_GXB 22656
#define OF_HS  22848
#define OF_RS  23360
#define OF_WIN 23872         // [2][8] ints
#define OF_XV  23888         // [2][8][8]
#define SM_MAIN 24016        // 96064 bytes

// K2 smem float offsets
#define SH_W1  0             // 128*68
#define SH_HB  8704          // 8 warps * 2 buffers * 512
#define SH_OB1 16896
#define SH_W2  17024
#define SH_OB2 17280
#define SM_HEAD 17282        // 69128 bytes

#define HEAD_L      6
#define HEAD_BLOCKS 1336     // 1336*8*48 = 513024 pairs

__device__ int   g_winner[NEV * B_];
__device__ float g_hrec[(size_t)(NSTEPS + 1) * B_ * 64];   // [t][b][64]

__global__ void winner_init_k() {
    int i = blockIdx.x * blockDim.x + threadIdx.x;
    if (i < NEV * B_) g_winner[i] = -1;
}
__global__ void winner_scatter_k(const int* __restrict__ sid) {
    int j = blockIdx.x * blockDim.x + threadIdx.x;
    if (j < TOT_) atomicMax(&g_winner[(j >> 8) * B_ + sid[j]], j);
}

__device__ __forceinline__ float sigm(float x) {
    return __fdividef(1.f, 1.f + __expf(-x));
}
__device__ __forceinline__ float tanh_f(float x) {        // exact-ish (events, h0)
    float xc = fminf(fmaxf(x, -15.f), 15.f);
    float e  = __expf(-2.f * xc);
    return __fdividef(1.f - e, 1.f + e);
}
__device__ __forceinline__ float tanh_fast(float x) {     // MUFU.TANH (ODE only)
    float y; asm("tanh.approx.f32 %0, %1;" : "=f"(y) : "f"(x));
    return y;
}
#define FMA2(d, a, b, c) \
    asm("fma.rn.f32x2 %0, %1, %2, %3;" : "=l"(d) : "l"(a), "l"(b), "l"(c))
__device__ __forceinline__ float hadd2(ull v) {
    unsigned lo, hi;
    asm("mov.b64 {%0, %1}, %2;" : "=r"(lo), "=r"(hi) : "l"(v));
    return __uint_as_float(lo) + __uint_as_float(hi);
}
// packed bf16x2 -> packed f32x2 (exact widening: shift / mask + pack)
__device__ __forceinline__ ull bf2up(unsigned u) {
    unsigned lo = u << 16;
    unsigned hi = u & 0xffff0000u;
    ull r; asm("mov.b64 %0, {%1, %2};" : "=l"(r) : "r"(lo), "r"(hi));
    return r;
}
__device__ __forceinline__ unsigned packbf(float a, float b) {
    __nv_bfloat162 t = __floats2bfloat162_rn(a, b);   // a->low, b->high
    unsigned u; __builtin_memcpy(&u, &t, 4);
    return u;
}
__device__ __forceinline__ float dot8(const float* __restrict__ w, float4 xa, float4 xb) {
    float4 A  = *reinterpret_cast<const float4*>(w);
    float4 Bv = *reinterpret_cast<const float4*>(w + 4);
    float s = A.x * xa.x;
    s = fmaf(A.y,  xa.y, s); s = fmaf(A.z,  xa.z, s); s = fmaf(A.w,  xa.w, s);
    s = fmaf(Bv.x, xb.x, s); s = fmaf(Bv.y, xb.y, s);
    s = fmaf(Bv.z, xb.z, s); s = fmaf(Bv.w, xb.w, s);
    return s;
}
#define CP_ASYNC16(saddr, gptr) \
    asm volatile("cp.async.cg.shared.global [%0], [%1], 16;" \
                 :: "r"(saddr), "l"(gptr) : "memory")
#define CP_COMMIT()  asm volatile("cp.async.commit_group;" ::: "memory")
#define CP_WAIT0()   asm volatile("cp.async.wait_group 0;" ::: "memory")

// GRU-Bayes event update, one sample, warp-collective (fp32 weights)
__device__ __forceinline__ void event_upd(
    float* __restrict__ hs, const float* __restrict__ xv,
    const float* __restrict__ sm,
    float ebr1, float ebr2, float ebz1, float ebz2,
    float ebi1, float ebi2, float ebh1, float ebh2,
    int lane, int o2)
{
    float4 xa = *(const float4*)xv, xb = *(const float4*)(xv + 4);
    float gir1 = dot8(sm + OF_WIH + lane*12,       xa, xb);
    float gir2 = dot8(sm + OF_WIH + (32+lane)*12,  xa, xb);
    float giz1 = dot8(sm + OF_WIH + (64+lane)*12,  xa, xb);
    float giz2 = dot8(sm + OF_WIH + (96+lane)*12,  xa, xb);
    float gin1 = dot8(sm + OF_WIH + (128+lane)*12, xa, xb);
    float gin2 = dot8(sm + OF_WIH + (160+lane)*12, xa, xb);
    const ul2* pE1 = (const ul2*)(sm + OF_WHH + lane*68);
    ull a1=0,a2=0,a3=0,a4=0,a5=0,a6=0;
    const ul2* hp = (const ul2*)hs;
    #pragma unroll
    for (int i = 0; i < 16; i++) {
        ul2 hv = hp[i];
        ul2 w1 = pE1[i],        w2 = pE1[i + 544];
        ul2 w3 = pE1[i + 1088], w4 = pE1[i + 1632];
        ul2 w5 = pE1[i + 2176], w6 = pE1[i + 2720];
        FMA2(a1, w1.x, hv.x, a1); FMA2(a1, w1.y, hv.y, a1);
        FMA2(a2, w2.x, hv.x, a2); FMA2(a2, w2.y, hv.y, a2);
        FMA2(a3, w3.x, hv.x, a3); FMA2(a3, w3.y, hv.y, a3);
        FMA2(a4, w4.x, hv.x, a4); FMA2(a4, w4.y, hv.y, a4);
        FMA2(a5, w5.x, hv.x, a5); FMA2(a5, w5.y, hv.y, a5);
        FMA2(a6, w6.x, hv.x, a6); FMA2(a6, w6.y, hv.y, a6);
    }
    float h1o = hs[lane], h2o = hs[o2];
    float r1 = sigm(gir1 + hadd2(a1) + ebr1);
    float r2 = sigm(gir2 + hadd2(a2) + ebr2);
    float z1 = sigm(giz1 + hadd2(a3) + ebz1);
    float z2 = sigm(giz2 + hadd2(a4) + ebz2);
    float n1 = tanh_f(gin1 + ebi1 + r1 * (hadd2(a5) + ebh1));
    float n2 = tanh_f(gin2 + ebi2 + r2 * (hadd2(a6) + ebh2));
    float h1n = fmaf(z1, h1o - n1, n1);      // (1-z)n + z h
    float h2n = fmaf(z2, h2o - n2, n2);
    __syncwarp();
    hs[lane] = h1n; hs[o2] = h2n;
    __syncwarp();
}

__global__ __launch_bounds__(128, 1)
void ev_gru_main(
    const float* __restrict__ X,
    const float* __restrict__ covs,
    const float* __restrict__ cW1, const float* __restrict__ cb1,
    const float* __restrict__ cW2, const float* __restrict__ cb2,
    const float* __restrict__ gWih, const float* __restrict__ gWhh,
    const float* __restrict__ gbih, const float* __restrict__ gbhh,
    const float* __restrict__ gxb,
    const float* __restrict__ ghrW, const float* __restrict__ ghzW,
    const float* __restrict__ ghhW)
{
    extern __shared__ float sm[];
    unsigned* usm = (unsigned*)sm;
    const int tid = threadIdx.x, blk = blockIdx.x;
    const int warp = tid >> 5, lane = tid & 31, o2 = lane + 32;
    int* swin = (int*)(sm + OF_WIN);

    // ---- staging: bf16x2-packed gate matrices, fp32 event matrices ----
    for (int i = tid; i < 64*32; i += 128) {
        int r = i >> 5, p = i & 31, c = p * 2;
        usm[UW_GHR + r*36 + p] = packbf(ghrW[r*64 + c], ghrW[r*64 + c + 1]);
        usm[UW_GHZ + r*36 + p] = packbf(ghzW[r*64 + c], ghzW[r*64 + c + 1]);
        usm[UW_GHH + r*36 + p] = packbf(ghhW[r*64 + c], ghhW[r*64 + c + 1]);
    }
    for (int i = tid; i < 192*64; i += 128) {
        int r = i >> 6, c = i & 63;
        sm[OF_WHH + r*68 + c] = gWhh[i];
    }
    for (int i = tid; i < 192*8; i += 128) {
        int r = i >> 3, c = i & 7;
        sm[OF_WIH + r*12 + c] = gWih[i];
    }
    for (int i = tid; i < 192; i += 128) {
        sm[OF_BIH + i] = gbih[i];
        sm[OF_BHH + i] = gbhh[i];
        sm[OF_GXB + i] = gxb[i];
    }

    const int sA = warp*2, sB = sA + 1;
    const int bA = blk*8 + sA, bB = bA + 1;
    float* hA = sm + OF_HS + sA*64;  float* hB = sm + OF_HS + sB*64;
    float* rA = sm + OF_RS + sA*64;  float* rB = sm + OF_RS + sB*64;

    // ---- h0 init (warp-local, 2 samples, fp32 global weights) ----
    #pragma unroll
    for (int pick = 0; pick < 2; pick++) {
        const int b = pick ? bB : bA;
        float* hs = pick ? hB : hA;
        float* rs = pick ? rB : rA;
        float t1 = __ldg(cb1 + lane), t2 = __ldg(cb1 + o2);
        #pragma unroll
        for (int k = 0; k < 16; k++) {
            float cv = __ldg(covs + b*16 + k);
            t1 = fmaf(cv, __ldg(cW1 + lane*16 + k), t1);
            t2 = fmaf(cv, __ldg(cW1 + o2*16   + k), t2);
        }
        rs[lane] = fmaxf(t1, 0.f); rs[o2] = fmaxf(t2, 0.f);
        __syncwarp();
        float a1 = __ldg(cb2 + lane), a2 = __ldg(cb2 + o2);
        #pragma unroll 8
        for (int c = 0; c < 64; c++) {
            float tv = rs[c];
            a1 = fmaf(tv, __ldg(cW2 + lane*64 + c), a1);
            a2 = fmaf(tv, __ldg(cW2 + o2*64   + c), a2);
        }
        __syncwarp();
        hs[lane] = tanh_f(a1); hs[o2] = tanh_f(a2);
        __syncwarp();
    }
    // t=0 winner/X prefetch (warp-local)
    if (lane < 2) {
        int w = __ldg(g_winner + bA + lane);
        swin[sA + lane] = w;
        if (w >= 0) {
            const float4* xp = (const float4*)(X + (size_t)w*8);
            float4 xa = __ldg(xp), xb = __ldg(xp + 1);
            float4* dst = (float4*)(sm + OF_XV + (sA + lane)*8);
            dst[0] = xa; dst[1] = xb;
        }
    }
    __syncthreads();   // staging done (one-time)

    // ---- stationary pointers / scalars ----
    const uint4* qR1 = (const uint4*)(usm + UW_GHR + lane*36);
    const uint4* qR2 = (const uint4*)(usm + UW_GHR + (lane+32)*36);
    const uint4* qZ1 = (const uint4*)(usm + UW_GHZ + lane*36);
    const uint4* qZ2 = (const uint4*)(usm + UW_GHZ + (lane+32)*36);
    const uint4* qU1 = (const uint4*)(usm + UW_GHH + lane*36);
    const uint4* qU2 = (const uint4*)(usm + UW_GHH + (lane+32)*36);
    const ul2* hpA = (const ul2*)hA;  const ul2* hpB = (const ul2*)hB;
    const ul2* rpA = (const ul2*)rA;  const ul2* rpB = (const ul2*)rB;

    const float xr1 = sm[OF_GXB + lane],       xr2 = sm[OF_GXB + o2];
    const float xz1 = sm[OF_GXB + 64 + lane],  xz2 = sm[OF_GXB + 64 + o2];
    const float xh1 = sm[OF_GXB + 128 + lane], xh2 = sm[OF_GXB + 128 + o2];
    const float ebr1 = sm[OF_BIH + lane]      + sm[OF_BHH + lane];
    const float ebr2 = sm[OF_BIH + o2]        + sm[OF_BHH + o2];
    const float ebz1 = sm[OF_BIH + 64 + lane] + sm[OF_BHH + 64 + lane];
    const float ebz2 = sm[OF_BIH + 64 + o2]   + sm[OF_BHH + 64 + o2];
    const float ebi1 = sm[OF_BIH + 128 + lane], ebi2 = sm[OF_BIH + 128 + o2];
    const float ebh1 = sm[OF_BHH + 128 + lane], ebh2 = sm[OF_BHH + 128 + o2];

    // ================= main loop (warp-independent) =================
    for (int t = 0; ; t++) {
        const int pb = t & 1;

        // ---- events (last-dup wins; from pre-update h; fp32 weights) ----
        if (t < NEV) {
            if (swin[pb*8 + sA] >= 0)
                event_upd(hA, sm + OF_XV + pb*64 + sA*8, sm,
                          ebr1,ebr2,ebz1,ebz2,ebi1,ebi2,ebh1,ebh2, lane, o2);
            if (swin[pb*8 + sB] >= 0)
                event_upd(hB, sm + OF_XV + pb*64 + sB*8, sm,
                          ebr1,ebr2,ebz1,ebz2,ebi1,ebi2,ebh1,ebh2, lane, o2);
        }

        // ---- h_rec store (post-event, pre-ODE) ----
        {
            float* base = g_hrec + ((size_t)t*B_ + bA)*64;
            float2 vA = *(const float2*)(hA + lane*2);
            float2 vB = *(const float2*)(hB + lane*2);
            *(float2*)(base + lane*2)      = vA;
            *(float2*)(base + 64 + lane*2) = vB;
        }
        if (t == NSTEPS) break;

        // warp-local prefetch of winners for t+1
        int pw = -1;
        const bool pf = (t + 1 < NEV) && (lane < 2);
        if (pf) pw = __ldg(g_winner + (t+1)*B_ + bA + lane);

        // ---- PASS1: gates r,z — bf16 weights unpacked to FMA2 ----
        ull aR1A=0, aR1B=0, aR2A=0, aR2B=0, aZ1A=0, aZ1B=0, aZ2A=0, aZ2B=0;
        #pragma unroll
        for (int i = 0; i < 8; i++) {
            ul2 a0 = hpA[2*i], a1 = hpA[2*i+1];
            ul2 b0 = hpB[2*i], b1 = hpB[2*i+1];
            uint4 q; ull w0, w1, w2, w3;
            q = qR1[i];
            w0 = bf2up(q.x); w1 = bf2up(q.y); w2 = bf2up(q.z); w3 = bf2up(q.w);
            FMA2(aR1A,w0,a0.x,aR1A); FMA2(aR1A,w1,a0.y,aR1A);
            FMA2(aR1A,w2,a1.x,aR1A); FMA2(aR1A,w3,a1.y,aR1A);
            FMA2(aR1B,w0,b0.x,aR1B); FMA2(aR1B,w1,b0.y,aR1B);
            FMA2(aR1B,w2,b1.x,aR1B); FMA2(aR1B,w3,b1.y,aR1B);
            q = qR2[i];
            w0 = bf2up(q.x); w1 = bf2up(q.y); w2 = bf2up(q.z); w3 = bf2up(q.w);
            FMA2(aR2A,w0,a0.x,aR2A); FMA2(aR2A,w1,a0.y,aR2A);
            FMA2(aR2A,w2,a1.x,aR2A); FMA2(aR2A,w3,a1.y,aR2A);
            FMA2(aR2B,w0,b0.x,aR2B); FMA2(aR2B,w1,b0.y,aR2B);
            FMA2(aR2B,w2,b1.x,aR2B); FMA2(aR2B,w3,b1.y,aR2B);
            q = qZ1[i];
            w0 = bf2up(q.x); w1 = bf2up(q.y); w2 = bf2up(q.z); w3 = bf2up(q.w);
            FMA2(aZ1A,w0,a0.x,aZ1A); FMA2(aZ1A,w1,a0.y,aZ1A);
            FMA2(aZ1A,w2,a1.x,aZ1A); FMA2(aZ1A,w3,a1.y,aZ1A);
            FMA2(aZ1B,w0,b0.x,aZ1B); FMA2(aZ1B,w1,b0.y,aZ1B);
            FMA2(aZ1B,w2,b1.x,aZ1B); FMA2(aZ1B,w3,b1.y,aZ1B);
            q = qZ2[i];
            w0 = bf2up(q.x); w1 = bf2up(q.y); w2 = bf2up(q.z); w3 = bf2up(q.w);
            FMA2(aZ2A,w0,a0.x,aZ2A); FMA2(aZ2A,w1,a0.y,aZ2A);
            FMA2(aZ2A,w2,a1.x,aZ2A); FMA2(aZ2A,w3,a1.y,aZ2A);
            FMA2(aZ2B,w0,b0.x,aZ2B); FMA2(aZ2B,w1,b0.y,aZ2B);
            FMA2(aZ2B,w2,b1.x,aZ2B); FMA2(aZ2B,w3,b1.y,aZ2B);
        }
        float h1A = hA[lane], h2A = hA[o2];
        float h1B = hB[lane], h2B = hB[o2];
        float r1A = sigm(hadd2(aR1A) + xr1), r2A = sigm(hadd2(aR2A) + xr2);
        float r1B = sigm(hadd2(aR1B) + xr1), r2B = sigm(hadd2(aR2B) + xr2);
        float z1A = sigm(hadd2(aZ1A) + xz1), z2A = sigm(hadd2(aZ2A) + xz2);
        float z1B = sigm(hadd2(aZ1B) + xz1), z2B = sigm(hadd2(aZ2B) + xz2);
        __syncwarp();
        rA[lane] = r1A * h1A; rA[o2] = r2A * h2A;
        rB[lane] = r1B * h1B; rB[o2] = r2B * h2B;
        if (pf) {
            swin[(pb ^ 1)*8 + sA + lane] = pw;
            if (pw >= 0) {
                const float4* xp = (const float4*)(X + (size_t)pw*8);
                float4 xa = __ldg(xp), xb = __ldg(xp + 1);
                float4* dst = (float4*)(sm + OF_XV + (pb^1)*64 + (sA+lane)*8);
                dst[0] = xa; dst[1] = xb;
            }
        }
        __syncwarp();

        // ---- PASS2: ghh (bf16) on (r*h); Euler update (fast tanh) ----
        ull u1A=0, u1B=0, u2A=0, u2B=0;
        #pragma unroll
        for (int i = 0; i < 8; i++) {
            ul2 a0 = rpA[2*i], a1 = rpA[2*i+1];
            ul2 b0 = rpB[2*i], b1 = rpB[2*i+1];
            uint4 q; ull w0, w1, w2, w3;
            q = qU1[i];
            w0 = bf2up(q.x); w1 = bf2up(q.y); w2 = bf2up(q.z); w3 = bf2up(q.w);
            FMA2(u1A,w0,a0.x,u1A); FMA2(u1A,w1,a0.y,u1A);
            FMA2(u1A,w2,a1.x,u1A); FMA2(u1A,w3,a1.y,u1A);
            FMA2(u1B,w0,b0.x,u1B); FMA2(u1B,w1,b0.y,u1B);
            FMA2(u1B,w2,b1.x,u1B); FMA2(u1B,w3,b1.y,u1B);
            q = qU2[i];
            w0 = bf2up(q.x); w1 = bf2up(q.y); w2 = bf2up(q.z); w3 = bf2up(q.w);
            FMA2(u2A,w0,a0.x,u2A); FMA2(u2A,w1,a0.y,u2A);
            FMA2(u2A,w2,a1.x,u2A); FMA2(u2A,w3,a1.y,u2A);
            FMA2(u2B,w0,b0.x,u2B); FMA2(u2B,w1,b0.y,u2B);
            FMA2(u2B,w2,b1.x,u2B); FMA2(u2B,w3,b1.y,u2B);
        }
        float uu1A = tanh_fast(xh1 + hadd2(u1A)), uu2A = tanh_fast(xh2 + hadd2(u2A));
        float uu1B = tanh_fast(xh1 + hadd2(u1B)), uu2B = tanh_fast(xh2 + hadd2(u2B));
        float h1An = fmaf(DT_*(1.f - z1A), uu1A - h1A, h1A);
        float h2An = fmaf(DT_*(1.f - z2A), uu2A - h2A, h2A);
        float h1Bn = fmaf(DT_*(1.f - z1B), uu1B - h1B, h1B);
        float h2Bn = fmaf(DT_*(1.f - z2B), uu2B - h2B, h2B);
        __syncwarp();
        hA[lane] = h1An; hA[o2] = h2An;
        hB[lane] = h1Bn; hB[o2] = h2Bn;
        __syncwarp();
    }
}

// ---------------- K2: batched head v3 (looped batches + cp.async) ----------
__global__ __launch_bounds__(256, 2)
void head_k(const float* __restrict__ oW1, const float* __restrict__ ob1,
            const float* __restrict__ oW2, const float* __restrict__ ob2,
            float* __restrict__ out)
{
    extern __shared__ float sm[];
    const int tid = threadIdx.x, warp = tid >> 5, lane = tid & 31;

    for (int i = tid; i < 128*64; i += 256) {
        int r = i >> 6, c = i & 63;
        sm[SH_W1 + r*68 + c] = oW1[i];
    }
    if (tid < 128) sm[SH_OB1 + tid] = ob1[tid];
    sm[SH_W2 + tid] = oW2[tid];
    if (tid < 2) sm[SH_OB2 + tid] = ob2[tid];

    const size_t warpbase = ((size_t)blockIdx.x*8 + warp) * (8*HEAD_L);
    const unsigned sbuf0 = (unsigned)__cvta_generic_to_shared(sm + SH_HB + warp*1024);
    const unsigned sbuf1 = sbuf0 + 512*4;

    {
        const float* g = g_hrec + warpbase*64;
        #pragma unroll
        for (int k = 0; k < 4; k++)
            CP_ASYNC16(sbuf0 + (lane + k*32)*16, g + (lane + k*32)*4);
        CP_COMMIT();
    }
    __syncthreads();
    CP_WAIT0();
    __syncwarp();

    const ul2* pA = (const ul2*)(sm + SH_W1 + lane*68);
    const ul2* pB = (const ul2*)(sm + SH_W1 + (lane+32)*68);
    const ul2* pC = (const ul2*)(sm + SH_W1 + (lane+64)*68);
    const ul2* pD = (const ul2*)(sm + SH_W1 + (lane+96)*68);
    const float bo0 = sm[SH_OB1 + lane],      bo1 = sm[SH_OB1 + lane + 32];
    const float bo2 = sm[SH_OB1 + lane + 64], bo3 = sm[SH_OB1 + lane + 96];
    const float wa0 = sm[SH_W2 + lane],        wa1 = sm[SH_W2 + 128 + lane];
    const float wb0 = sm[SH_W2 + 32 + lane],   wb1 = sm[SH_W2 + 160 + lane];
    const float wc0 = sm[SH_W2 + 64 + lane],   wc1 = sm[SH_W2 + 192 + lane];
    const float wd0 = sm[SH_W2 + 96 + lane],   wd1 = sm[SH_W2 + 224 + lane];
    const float b20 = sm[SH_OB2], b21 = sm[SH_OB2 + 1];

    for (int l = 0; l < HEAD_L; l++) {
        const int pb = l & 1;
        if (l + 1 < HEAD_L) {
            const float* g = g_hrec + (warpbase + (size_t)(l+1)*8)*64;
            const unsigned dst = pb ? sbuf0 : sbuf1;
            #pragma unroll
            for (int k = 0; k < 4; k++)
                CP_ASYNC16(dst + (lane + k*32)*16, g + (lane + k*32)*4);
            CP_COMMIT();
        }
        const ul2* hw = (const ul2*)(sm + SH_HB + warp*1024 + pb*512);

        ull aA[8], aB[8], aC[8], aD[8];
        #pragma unroll
        for (int p = 0; p < 8; p++) { aA[p]=0; aB[p]=0; aC[p]=0; aD[p]=0; }
        #pragma unroll
        for (int i = 0; i < 16; i++) {
            ul2 wa = pA[i], wb = pB[i], wc = pC[i], wd = pD[i];
            #pragma unroll
            for (int p = 0; p < 8; p++) {
                ul2 hv = hw[p*16 + i];
                FMA2(aA[p], wa.x, hv.x, aA[p]); FMA2(aA[p], wa.y, hv.y, aA[p]);
                FMA2(aB[p], wb.x, hv.x, aB[p]); FMA2(aB[p], wb.y, hv.y, aB[p]);
                FMA2(aC[p], wc.x, hv.x, aC[p]); FMA2(aC[p], wc.y, hv.y, aC[p]);
                FMA2(aD[p], wd.x, hv.x, aD[p]); FMA2(aD[p], wd.y, hv.y, aD[p]);
            }
        }
        const size_t base = warpbase + (size_t)l*8;
        #pragma unroll
        for (int p = 0; p < 8; p++) {
            float d0 = fmaxf(hadd2(aA[p]) + bo0, 0.f);
            float d1 = fmaxf(hadd2(aB[p]) + bo1, 0.f);
            float d2 = fmaxf(hadd2(aC[p]) + bo2, 0.f);
            float d3 = fmaxf(hadd2(aD[p]) + bo3, 0.f);
            float p0 = d0*wa0; p0 = fmaf(d1,wb0,p0); p0 = fmaf(d2,wc0,p0); p0 = fmaf(d3,wd0,p0);
            float p1 = d0*wa1; p1 = fmaf(d1,wb1,p1); p1 = fmaf(d2,wc1,p1); p1 = fmaf(d3,wd1,p1);
            #pragma unroll
            for (int s = 16; s > 0; s >>= 1) {
                p0 += __shfl_xor_sync(0xffffffffu, p0, s);
                p1 += __shfl_xor_sync(0xffffffffu, p1, s);
            }
            if (lane == 0) {
                float2 v = {p0 + b20, p1 + b21};
                *(float2*)(out + (base + p)*2) = v;
            }
        }
        if (l + 1 < HEAD_L) {
            CP_WAIT0();
            __syncwarp();
        }
    }
}

extern "C" void kernel_launch(void* const* d_in, const int* in_sizes, int n_in,
                              void* d_out, int out_size)
{
    (void)in_sizes; (void)n_in; (void)out_size;
    const float* X    = (const float*)d_in[2];
    const int*   sid  = (const int*)  d_in[3];
    const float* covs = (const float*)d_in[4];
    const float* cW1  = (const float*)d_in[6];
    const float* cb1  = (const float*)d_in[7];
    const float* cW2  = (const float*)d_in[8];
    const float* cb2  = (const float*)d_in[9];
    const float* gWih = (const float*)d_in[10];
    const float* gWhh = (const float*)d_in[11];
    const float* gbih = (const float*)d_in[12];
    const float* gbhh = (const float*)d_in[13];
    const float* gxb  = (const float*)d_in[15];
    const float* ghrW = (const float*)d_in[16];
    const float* ghzW = (const float*)d_in[17];
    const float* ghhW = (const float*)d_in[18];
    const float* oW1  = (const float*)d_in[19];
    const float* ob1  = (const float*)d_in[20];
    const float* oW2  = (const float*)d_in[21];
    const float* ob2  = (const float*)d_in[22];
    float* out = (float*)d_out;

    winner_init_k<<<(NEV*B_ + 255)/256, 256>>>();
    winner_scatter_k<<<(TOT_ + 255)/256, 256>>>(sid);

    size_t sm_main = SM_MAIN * sizeof(float);
    cudaFuncSetAttribute(ev_gru_main, cudaFuncAttributeMaxDynamicSharedMemorySize, (int)sm_main);
    ev_gru_main<<<B_/8, 128, sm_main>>>(X, covs, cW1, cb1, cW2, cb2,
                                        gWih, gWhh, gbih, gbhh, gxb,
                                        ghrW, ghzW, ghhW);

    size_t sm_head = SM_HEAD * sizeof(float);
    cudaFuncSetAttribute(head_k, cudaFuncAttributeMaxDynamicSharedMemorySize, (int)sm_head);
    head_k<<<HEAD_BLOCKS, 256, sm_head>>>(oW1, ob1, oW2, ob2, out);
}